// round 1
// baseline (speedup 1.0000x reference)
#include <cuda_runtime.h>

// ---------------------------------------------------------------------------
// OverISS_T: over-determined ISS with dereverberation (OverISS-T), B=2, C=6,
// S=2, F=257, N=1000, T=5 taps, 2 iterations, projection back to mic 0.
// ---------------------------------------------------------------------------

#define DEVFN __device__ __forceinline__

namespace cfg {
constexpr int B = 2, C = 6, S = 2, F = 257, N = 1000, T = 5;
constexpr int CB = C - S;          // 4 background channels
constexpr int PAD = 6;             // N_TAPS + N_DELAY
constexpr int ROW = 1008;          // padded row length for X in smem
constexpr int NBF = B * F;         // 514 blocks
constexpr int NT = 256;            // threads per block (8 warps)
constexpr float EPS = 1e-3f;
constexpr float MODEL_EPS = 1e-5f;
constexpr float PB_EPS = 1e-6f;
}

using namespace cfg;

// ------------------------- global scratch (static) -------------------------
__device__ float2 gY[B * S * F * N];          // demixed sources
__device__ float2 gW[B * F * S * C];          // demix filters
__device__ float2 gH[B * F * S * C * T];      // derev filters
__device__ float2 gCXX[B * F * C * C];        // covariance X X^H
__device__ float2 gCXbX[B * F * C * T * C];   // covariance Xbar X^H
__device__ float  gWt[B * S * N];             // weights (per b,s,n)
__device__ float  gGs[B * S];                 // g_sqrt per (b,s)

// ------------------------- complex helpers -------------------------
DEVFN float2 cmul(float2 a, float2 b) { return make_float2(a.x*b.x - a.y*b.y, a.x*b.y + a.y*b.x); }
DEVFN float2 cadd(float2 a, float2 b) { return make_float2(a.x + b.x, a.y + b.y); }
DEVFN float2 csub(float2 a, float2 b) { return make_float2(a.x - b.x, a.y - b.y); }
DEVFN float2 conjf2(float2 a)         { return make_float2(a.x, -a.y); }
DEVFN float2 cdiv(float2 a, float2 b) {
    float d = b.x*b.x + b.y*b.y;
    return make_float2((a.x*b.x + a.y*b.y) / d, (a.y*b.x - a.x*b.y) / d);
}

// load padded X rows into smem: Xs[d][j] = X_pad[j], j in [0,ROW)
DEVFN void load_Xpad(float2* Xs, const float* __restrict__ Xr,
                     const float* __restrict__ Xi, int b, int f, int tid) {
    for (int i = tid; i < C * ROW; i += NT) {
        int d = i / ROW, j = i % ROW;
        float2 v = make_float2(0.f, 0.f);
        if (j >= PAD && j < PAD + N) {
            int gi = ((b * C + d) * F + f) * N + (j - PAD);
            v = make_float2(Xr[gi], Xi[gi]);
        }
        Xs[i] = v;
    }
}

// ===========================================================================
// Kernel 1: covariances + init of Y, W, H  (one block per (b,f))
// ===========================================================================
__global__ void __launch_bounds__(NT) k_pre(const float* __restrict__ Xr,
                                            const float* __restrict__ Xi) {
    extern __shared__ float2 smp[];
    float2* Xs = smp;   // C*ROW

    const int bf = blockIdx.x;
    const int b = bf / F, f = bf % F;
    const int tid = threadIdx.x;
    const int warp = tid >> 5, lane = tid & 31;

    load_Xpad(Xs, Xr, Xi, b, f, tid);
    __syncthreads();

    // 36 C_XX outputs + 180 C_XbarX outputs, one warp per output
    for (int o = warp; o < C * C + C * T * C; o += NT / 32) {
        const float2 *pa, *pb;
        if (o < C * C) {
            int c = o / C, d = o % C;
            pa = Xs + c * ROW + PAD;        // X[c]
            pb = Xs + d * ROW + PAD;        // X[d]
        } else {
            int o2 = o - C * C;
            int d = o2 / (T * C), t = (o2 / C) % T, c = o2 % C;
            pa = Xs + d * ROW + t;          // Xbar[d][t][n] = X_pad[t+n]
            pb = Xs + c * ROW + PAD;        // X[c]
        }
        float ar = 0.f, ai = 0.f;
        for (int n = lane; n < N; n += 32) {
            float2 a = pa[n], bb = pb[n];   // a * conj(b)
            ar += a.x * bb.x + a.y * bb.y;
            ai += a.y * bb.x - a.x * bb.y;
        }
#pragma unroll
        for (int off = 16; off > 0; off >>= 1) {
            ar += __shfl_down_sync(0xffffffffu, ar, off);
            ai += __shfl_down_sync(0xffffffffu, ai, off);
        }
        if (lane == 0) {
            float2 r = make_float2(ar / (float)N, ai / (float)N);
            if (o < C * C) gCXX[bf * C * C + o] = r;
            else           gCXbX[bf * C * T * C + (o - C * C)] = r;
        }
    }

    // init Y = X[:S], W = eye, H = 0
    for (int n = tid; n < N; n += NT) {
        gY[((b * S + 0) * F + f) * N + n] = Xs[0 * ROW + PAD + n];
        gY[((b * S + 1) * F + f) * N + n] = Xs[1 * ROW + PAD + n];
    }
    if (tid < S * C) {
        int s = tid / C, c = tid % C;
        gW[bf * S * C + tid] = make_float2((s == c) ? 1.f : 0.f, 0.f);
    }
    for (int i = tid; i < S * C * T; i += NT)
        gH[bf * S * C * T + i] = make_float2(0.f, 0.f);
}

// ===========================================================================
// Kernel 2: Laplace model weights + g  (one block per (b,s))
// ===========================================================================
__global__ void __launch_bounds__(1024) k_weights() {
    const int bs = blockIdx.x;          // b*S + s
    const int tid = threadIdx.x;

    float P = 0.f;
    if (tid < N) {
        const float2* py = gY + (size_t)bs * F * N + tid;
        for (int f = 0; f < F; f++) {
            float2 v = py[(size_t)f * N];
            P += v.x * v.x + v.y * v.y;
        }
    }
    __shared__ float red[32];
    float t = P;
#pragma unroll
    for (int off = 16; off > 0; off >>= 1) t += __shfl_down_sync(0xffffffffu, t, off);
    if ((tid & 31) == 0) red[tid >> 5] = t;
    __syncthreads();
    __shared__ float g_sh;
    if (tid < 32) {
        float v = red[tid];
#pragma unroll
        for (int off = 16; off > 0; off >>= 1) v += __shfl_down_sync(0xffffffffu, v, off);
        if (tid == 0) {
            float g = fmaxf(v / (float)(F * N), EPS);   // g = max(mean |Y|^2, eps)
            g_sh = g;
            gGs[bs] = sqrtf(g);
        }
    }
    __syncthreads();
    if (tid < N) {
        // weights = g / max(2*sqrt(sum_f |Y|^2), 1e-5)
        gWt[bs * N + tid] = g_sh / fmaxf(2.f * sqrtf(P), MODEL_EPS);
    }
}

// ===========================================================================
// Kernel 3: one full OverISS iteration per (b,f): scale, J-solve, Z, 36 ISS steps
// ===========================================================================
__global__ void __launch_bounds__(NT) k_iter(const float* __restrict__ Xr,
                                             const float* __restrict__ Xi) {
    extern __shared__ float2 smi[];
    float2* Xs = smi;                  // C*ROW
    float2* Ys = Xs + C * ROW;         // S*N
    float2* Zs = Ys + S * N;           // CB*N
    float2* sW = Zs + CB * N;          // S*C
    float2* sH = sW + S * C;           // S*C*T
    float2* sJ = sH + S * C * T;       // CB*S
    float2* sA = sJ + CB * S;          // S*C
    float2* sv = sA + S * C;           // 2
    float*  ws = (float*)(sv + 2);     // S*N
    float*  red = ws + S * N;          // 8 warps * 6

    const int bf = blockIdx.x;
    const int b = bf / F, f = bf % F;
    const int tid = threadIdx.x;
    const int warp = tid >> 5, lane = tid & 31;

    const float gs0 = fmaxf(gGs[b * S + 0], EPS);
    const float gs1 = fmaxf(gGs[b * S + 1], EPS);

    load_Xpad(Xs, Xr, Xi, b, f, tid);
    for (int n = tid; n < N; n += NT) {
        float2 y0 = gY[((b * S + 0) * F + f) * N + n];
        float2 y1 = gY[((b * S + 1) * F + f) * N + n];
        Ys[n]     = make_float2(y0.x / gs0, y0.y / gs0);
        Ys[N + n] = make_float2(y1.x / gs1, y1.y / gs1);
        ws[n]     = gWt[(b * S + 0) * N + n];
        ws[N + n] = gWt[(b * S + 1) * N + n];
    }
    if (tid < S * C) {
        float g = (tid < C) ? gs0 : gs1;
        float2 w = gW[bf * S * C + tid];
        sW[tid] = make_float2(w.x / g, w.y / g);
    }
    if (tid < S * C * T) {
        float g = (tid < C * T) ? gs0 : gs1;
        float2 h = gH[bf * S * C * T + tid];
        sH[tid] = make_float2(h.x / g, h.y / g);
    }
    __syncthreads();

    // --- background update: A = W C_XX + H C_XbarX ; 2x2 solve with 4 RHS ---
    if (tid < S * C) {
        int s = tid / C, d = tid % C;
        const float2* cxx = gCXX + bf * C * C;
        const float2* cbx = gCXbX + bf * C * T * C;
        float2 acc = make_float2(0.f, 0.f);
        for (int c = 0; c < C; c++) acc = cadd(acc, cmul(sW[s * C + c], cxx[c * C + d]));
        for (int dd = 0; dd < C; dd++)
            for (int t = 0; t < T; t++)
                acc = cadd(acc, cmul(sH[(s * C + dd) * T + t], cbx[(dd * T + t) * C + d]));
        sA[s * C + d] = acc;
    }
    __syncthreads();
    if (tid == 0) {
        float2 M00 = sA[0], M01 = sA[1], M10 = sA[C], M11 = sA[C + 1];
        float2 det = csub(cmul(M00, M11), cmul(M01, M10));
        for (int k = 0; k < CB; k++) {
            float2 r0 = sA[2 + k], r1 = sA[C + 2 + k];
            float2 jh0 = cdiv(csub(cmul(M11, r0), cmul(M01, r1)), det);
            float2 jh1 = cdiv(csub(cmul(M00, r1), cmul(M10, r0)), det);
            sJ[k * S + 0] = conjf2(jh0);
            sJ[k * S + 1] = conjf2(jh1);
        }
    }
    __syncthreads();

    // --- Z = J X[:S] - X[S:] ---
    for (int i = tid; i < CB * N; i += NT) {
        int k = i / N, n = i % N;
        float2 z = cmul(sJ[k * S + 0], Xs[0 * ROW + PAD + n]);
        z = cadd(z, cmul(sJ[k * S + 1], Xs[1 * ROW + PAD + n]));
        z = csub(z, Xs[(S + k) * ROW + PAD + n]);
        Zs[i] = z;
    }
    __syncthreads();

    // --- 36 sequential ISS steps ---
    for (int step = 0; step < 2 + CB + C * T; step++) {
        const float2* Xp;
        if (step < 2)             Xp = Ys + step * N;
        else if (step < 2 + CB)   Xp = Zs + (step - 2) * N;
        else {
            int q = step - 2 - CB;
            Xp = Xs + (q / T) * ROW + (q % T);
        }

        float nr0 = 0.f, ni0 = 0.f, de0 = 0.f, nr1 = 0.f, ni1 = 0.f, de1 = 0.f;
        for (int n = tid; n < N; n += NT) {
            float2 xv = Xp[n];
            float m = xv.x * xv.x + xv.y * xv.y;
            float w0 = ws[n], w1 = ws[N + n];
            float2 y0 = Ys[n], y1 = Ys[N + n];
            nr0 += w0 * (y0.x * xv.x + y0.y * xv.y);
            ni0 += w0 * (y0.y * xv.x - y0.x * xv.y);
            de0 += w0 * m;
            nr1 += w1 * (y1.x * xv.x + y1.y * xv.y);
            ni1 += w1 * (y1.y * xv.x - y1.x * xv.y);
            de1 += w1 * m;
        }
#pragma unroll
        for (int off = 16; off > 0; off >>= 1) {
            nr0 += __shfl_down_sync(0xffffffffu, nr0, off);
            ni0 += __shfl_down_sync(0xffffffffu, ni0, off);
            de0 += __shfl_down_sync(0xffffffffu, de0, off);
            nr1 += __shfl_down_sync(0xffffffffu, nr1, off);
            ni1 += __shfl_down_sync(0xffffffffu, ni1, off);
            de1 += __shfl_down_sync(0xffffffffu, de1, off);
        }
        if (lane == 0) {
            red[warp * 6 + 0] = nr0; red[warp * 6 + 1] = ni0; red[warp * 6 + 2] = de0;
            red[warp * 6 + 3] = nr1; red[warp * 6 + 4] = ni1; red[warp * 6 + 5] = de1;
        }
        __syncthreads();
        if (tid == 0) {
            float s0 = 0, s1 = 0, s2 = 0, s3 = 0, s4 = 0, s5 = 0;
            for (int w = 0; w < NT / 32; w++) {
                s0 += red[w * 6 + 0]; s1 += red[w * 6 + 1]; s2 += red[w * 6 + 2];
                s3 += red[w * 6 + 3]; s4 += red[w * 6 + 4]; s5 += red[w * 6 + 5];
            }
            if (step < 2) {
                const float invN = 1.f / (float)N;
                s0 *= invN; s1 *= invN; s2 *= invN; s3 *= invN; s4 *= invN; s5 *= invN;
            }
            float d0 = fmaxf(s2, EPS), d1 = fmaxf(s5, EPS);
            float2 v0 = make_float2(s0 / d0, s1 / d0);
            float2 v1 = make_float2(s3 / d1, s4 / d1);

            if (step < 2) {
                int src = step, oth = 1 - src;
                float den_s = (src == 0) ? s2 : s5;
                float vsr = 1.f - 1.f / sqrtf(fmaxf(den_s, EPS));
                if (src == 0) v0 = make_float2(vsr, 0.f); else v1 = make_float2(vsr, 0.f);
                float2 vo = (src == 0) ? v1 : v0;
                float2 vs2 = (src == 0) ? v0 : v1;
                // other row first (reads original src row), then src row in place
                for (int d = 0; d < C; d++)
                    sW[oth * C + d] = csub(sW[oth * C + d], cmul(vo, sW[src * C + d]));
                for (int i = 0; i < C * T; i++)
                    sH[oth * C * T + i] = csub(sH[oth * C * T + i], cmul(vo, sH[src * C * T + i]));
                for (int d = 0; d < C; d++)
                    sW[src * C + d] = csub(sW[src * C + d], cmul(vs2, sW[src * C + d]));
                for (int i = 0; i < C * T; i++)
                    sH[src * C * T + i] = csub(sH[src * C * T + i], cmul(vs2, sH[src * C * T + i]));
            } else if (step < 2 + CB) {
                int k = step - 2;
                sW[0 * C + 0] = csub(sW[0 * C + 0], cmul(v0, sJ[k * S + 0]));
                sW[0 * C + 1] = csub(sW[0 * C + 1], cmul(v0, sJ[k * S + 1]));
                sW[0 * C + S + k] = cadd(sW[0 * C + S + k], v0);
                sW[1 * C + 0] = csub(sW[1 * C + 0], cmul(v1, sJ[k * S + 0]));
                sW[1 * C + 1] = csub(sW[1 * C + 1], cmul(v1, sJ[k * S + 1]));
                sW[1 * C + S + k] = cadd(sW[1 * C + S + k], v1);
            } else {
                int q = step - 2 - CB;
                int d = q / T, t = q % T;
                sH[(0 * C + d) * T + t] = cadd(sH[(0 * C + d) * T + t], v0);
                sH[(1 * C + d) * T + t] = cadd(sH[(1 * C + d) * T + t], v1);
            }
            sv[0] = v0; sv[1] = v1;
        }
        __syncthreads();
        {
            float2 v0 = sv[0], v1 = sv[1];
            for (int n = tid; n < N; n += NT) {
                float2 xv = Xp[n];  // read BEFORE writing (Xp may alias Ys[src])
                float2 y0 = Ys[n], y1 = Ys[N + n];
                Ys[n]     = csub(y0, cmul(v0, xv));
                Ys[N + n] = csub(y1, cmul(v1, xv));
            }
        }
        __syncthreads();
    }

    // --- write back ---
    for (int n = tid; n < N; n += NT) {
        gY[((b * S + 0) * F + f) * N + n] = Ys[n];
        gY[((b * S + 1) * F + f) * N + n] = Ys[N + n];
    }
    if (tid < S * C) gW[bf * S * C + tid] = sW[tid];
    if (tid < S * C * T) gH[bf * S * C * T + tid] = sH[tid];
}

// ===========================================================================
// Kernel 4: final J, demix+derev, projection back, write output
// ===========================================================================
__global__ void __launch_bounds__(NT) k_fin(const float* __restrict__ Xr,
                                            const float* __restrict__ Xi,
                                            float* __restrict__ out) {
    extern __shared__ float2 smf[];
    float2* Xs = smf;                 // C*ROW
    float2* sW = Xs + C * ROW;        // S*C
    float2* sH = sW + S * C;          // S*C*T
    float2* sJ = sH + S * C * T;      // CB*S
    float2* sA = sJ + CB * S;         // S*C
    float2* sa = sA + S * C;          // 2

    const int bf = blockIdx.x;
    const int b = bf / F, f = bf % F;
    const int tid = threadIdx.x;

    load_Xpad(Xs, Xr, Xi, b, f, tid);
    if (tid < S * C) sW[tid] = gW[bf * S * C + tid];
    if (tid < S * C * T) sH[tid] = gH[bf * S * C * T + tid];
    __syncthreads();

    if (tid < S * C) {
        int s = tid / C, d = tid % C;
        const float2* cxx = gCXX + bf * C * C;
        const float2* cbx = gCXbX + bf * C * T * C;
        float2 acc = make_float2(0.f, 0.f);
        for (int c = 0; c < C; c++) acc = cadd(acc, cmul(sW[s * C + c], cxx[c * C + d]));
        for (int dd = 0; dd < C; dd++)
            for (int t = 0; t < T; t++)
                acc = cadd(acc, cmul(sH[(s * C + dd) * T + t], cbx[(dd * T + t) * C + d]));
        sA[s * C + d] = acc;
    }
    __syncthreads();
    if (tid == 0) {
        // J = conj(solve(A[:, :S], A[:, S:]))
        float2 M00 = sA[0], M01 = sA[1], M10 = sA[C], M11 = sA[C + 1];
        float2 det = csub(cmul(M00, M11), cmul(M01, M10));
        for (int k = 0; k < CB; k++) {
            float2 r0 = sA[2 + k], r1 = sA[C + 2 + k];
            float2 jh0 = cdiv(csub(cmul(M11, r0), cmul(M01, r1)), det);
            float2 jh1 = cdiv(csub(cmul(M00, r1), cmul(M10, r0)), det);
            sJ[k * S + 0] = conjf2(jh0);
            sJ[k * S + 1] = conjf2(jh1);
        }
        // projection back: B[s][k] = sum_c W2[s][c] J[c][k] + W1[s][k]
        float2 Bm[2][2];
        for (int s = 0; s < S; s++)
            for (int k = 0; k < S; k++) {
                float2 acc = sW[s * C + k];
                for (int c = 0; c < CB; c++)
                    acc = cadd(acc, cmul(sW[s * C + S + c], sJ[c * S + k]));
                Bm[s][k] = acc;
            }
        // M[c][s] = B[s][c] + pb_eps * I ; solve M a = e_0
        float2 P00 = make_float2(Bm[0][0].x + PB_EPS, Bm[0][0].y);
        float2 P01 = Bm[1][0];
        float2 P10 = Bm[0][1];
        float2 P11 = make_float2(Bm[1][1].x + PB_EPS, Bm[1][1].y);
        float2 pdet = csub(cmul(P00, P11), cmul(P01, P10));
        sa[0] = cdiv(P11, pdet);
        sa[1] = cdiv(make_float2(-P10.x, -P10.y), pdet);
    }
    __syncthreads();

    float2 a0 = sa[0], a1 = sa[1];
    for (int n = tid; n < N; n += NT) {
#pragma unroll
        for (int s = 0; s < S; s++) {
            float2 y = make_float2(0.f, 0.f);
            for (int d = 0; d < C; d++)
                y = cadd(y, cmul(sW[s * C + d], Xs[d * ROW + PAD + n]));
            for (int d = 0; d < C; d++)
#pragma unroll
                for (int t = 0; t < T; t++)
                    y = csub(y, cmul(sH[(s * C + d) * T + t], Xs[d * ROW + t + n]));
            y = cmul(y, (s == 0) ? a0 : a1);
            size_t oi = ((size_t)((b * S + s) * F + f) * N + n) * 2;
            out[oi]     = y.x;
            out[oi + 1] = y.y;
        }
    }
}

// ===========================================================================
// launch
// ===========================================================================
namespace {
constexpr size_t SMEM_PRE  = sizeof(float2) * (size_t)(C * ROW);
constexpr size_t SMEM_ITER = sizeof(float2) * (size_t)(C * ROW + S * N + CB * N +
                                                       S * C + S * C * T + CB * S + S * C + 2)
                           + sizeof(float) * (size_t)(S * N + 48);
constexpr size_t SMEM_FIN  = sizeof(float2) * (size_t)(C * ROW + S * C + S * C * T +
                                                       CB * S + S * C + 2);
}

extern "C" void kernel_launch(void* const* d_in, const int* in_sizes, int n_in,
                              void* d_out, int out_size) {
    (void)in_sizes; (void)n_in; (void)out_size;
    const float* Xr = (const float*)d_in[0];
    const float* Xi = (const float*)d_in[1];
    float* out = (float*)d_out;

    cudaFuncSetAttribute(k_iter, cudaFuncAttributeMaxDynamicSharedMemorySize, (int)SMEM_ITER);
    cudaFuncSetAttribute(k_fin,  cudaFuncAttributeMaxDynamicSharedMemorySize, (int)SMEM_FIN);

    k_pre<<<NBF, NT, SMEM_PRE>>>(Xr, Xi);
    for (int it = 0; it < 2; it++) {
        k_weights<<<B * S, 1024>>>();
        k_iter<<<NBF, NT, SMEM_ITER>>>(Xr, Xi);
    }
    k_fin<<<NBF, NT, SMEM_FIN>>>(Xr, Xi, out);
}

// round 2
// speedup vs baseline: 2.0822x; 2.0822x over previous
#include <cuda_runtime.h>

// ---------------------------------------------------------------------------
// OverISS_T: over-determined ISS with dereverberation, B=2, C=6, S=2, F=257,
// N=1000, T=5 taps, 2 iterations, projection back to mic 0.
// R2: register-resident Y/w in k_iter (4 CTAs/SM, one wave), register-tiled
// covariance in k_pre, parallel weight reduction (k_ps + k_wt).
// ---------------------------------------------------------------------------

#define DEVFN __device__ __forceinline__

namespace cfg {
constexpr int B = 2, C = 6, S = 2, F = 257, N = 1000, T = 5;
constexpr int CB = C - S;          // 4 background channels
constexpr int PAD = 6;             // N_TAPS + N_DELAY
constexpr int ROW = 1032;          // padded row length (covers n up to 1023 + PAD)
constexpr int NBF = B * F;         // 514 blocks
constexpr int NT = 256;            // threads per block (8 warps)
constexpr float EPS = 1e-3f;
constexpr float MODEL_EPS = 1e-5f;
constexpr float PB_EPS = 1e-6f;
}
using namespace cfg;

// ------------------------- global scratch (static) -------------------------
__device__ float2 gY[B * S * F * N];
__device__ float2 gW[B * F * S * C];
__device__ float2 gH[B * F * S * C * T];
__device__ float2 gCXX[B * F * C * C];
__device__ float2 gCXbX[B * F * C * T * C];
__device__ float  gWt[B * S * N];          // weights per (b,s,n)
__device__ float  gP[B * S * N];           // sum_f |Y|^2 per (b,s,n)
__device__ float  gGs[B * S];              // g_sqrt per (b,s)

// ------------------------- complex helpers -------------------------
DEVFN float2 cmul(float2 a, float2 b) { return make_float2(a.x*b.x - a.y*b.y, a.x*b.y + a.y*b.x); }
DEVFN float2 cadd(float2 a, float2 b) { return make_float2(a.x + b.x, a.y + b.y); }
DEVFN float2 csub(float2 a, float2 b) { return make_float2(a.x - b.x, a.y - b.y); }
DEVFN float2 conjf2(float2 a)         { return make_float2(a.x, -a.y); }
DEVFN float2 cdiv(float2 a, float2 b) {
    float d = b.x*b.x + b.y*b.y;
    return make_float2((a.x*b.x + a.y*b.y) / d, (a.y*b.x - a.x*b.y) / d);
}

// load padded X rows into smem, zero outside [PAD, PAD+N)
DEVFN void load_Xpad(float2* Xs, const float* __restrict__ Xr,
                     const float* __restrict__ Xi, int b, int f, int tid) {
    for (int i = tid; i < C * ROW; i += NT) {
        int d = i / ROW, j = i % ROW;
        float2 v = make_float2(0.f, 0.f);
        if (j >= PAD && j < PAD + N) {
            int gi = ((b * C + d) * F + f) * N + (j - PAD);
            v = make_float2(Xr[gi], Xi[gi]);
        }
        Xs[i] = v;
    }
}

// ===========================================================================
// Kernel 1: covariances (register-tiled) + init of Y, W, H
// ===========================================================================
__global__ void __launch_bounds__(NT, 4) k_pre(const float* __restrict__ Xr,
                                               const float* __restrict__ Xi) {
    extern __shared__ float2 smp[];
    float2* Xs = smp;   // C*ROW

    const int bf = blockIdx.x;
    const int b = bf / F, f = bf % F;
    const int tid = threadIdx.x;
    const int warp = tid >> 5, lane = tid & 31;

    load_Xpad(Xs, Xr, Xi, b, f, tid);
    __syncthreads();

    // 18 groups: (d, c-pair). Each warp computes 12 outputs per group:
    // 5 taps x 2 c's (Xbar_{d,t} conj(X_c)) + 2 C_XX entries (X_c conj(X_d)).
#define ACCP(j, A, Bv) { ar[j] += (A).x*(Bv).x + (A).y*(Bv).y; \
                         ai[j] += (A).y*(Bv).x - (A).x*(Bv).y; }
#pragma unroll 1
    for (int g = warp; g < 18; g += NT / 32) {
        int d = g / 3, p = g % 3, c0 = 2 * p;
        const float2* ad = Xs + d * ROW;            // Xpad row d
        const float2* b0 = Xs + c0 * ROW + PAD;     // X row c0
        const float2* b1 = b0 + ROW;                // X row c0+1
        float ar[12], ai[12];
#pragma unroll
        for (int j = 0; j < 12; j++) { ar[j] = 0.f; ai[j] = 0.f; }
        for (int n = lane; n < N; n += 32) {
            float2 a0 = ad[n], a1 = ad[n+1], a2 = ad[n+2], a3 = ad[n+3], a4 = ad[n+4];
            float2 a6 = ad[n+6];                    // X[d][n]
            float2 u = b0[n], v = b1[n];
            ACCP(0, a0, u); ACCP(1, a1, u); ACCP(2, a2, u); ACCP(3, a3, u); ACCP(4, a4, u);
            ACCP(5, a0, v); ACCP(6, a1, v); ACCP(7, a2, v); ACCP(8, a3, v); ACCP(9, a4, v);
            ACCP(10, u, a6); ACCP(11, v, a6);
        }
#pragma unroll
        for (int off = 16; off > 0; off >>= 1)
#pragma unroll
            for (int j = 0; j < 12; j++) {
                ar[j] += __shfl_down_sync(0xffffffffu, ar[j], off);
                ai[j] += __shfl_down_sync(0xffffffffu, ai[j], off);
            }
        if (lane == 0) {
            const float invN = 1.f / (float)N;
#pragma unroll
            for (int t = 0; t < T; t++) {
                gCXbX[bf * C * T * C + (d * T + t) * C + c0]     = make_float2(ar[t] * invN, ai[t] * invN);
                gCXbX[bf * C * T * C + (d * T + t) * C + c0 + 1] = make_float2(ar[5 + t] * invN, ai[5 + t] * invN);
            }
            gCXX[bf * C * C + c0 * C + d]       = make_float2(ar[10] * invN, ai[10] * invN);
            gCXX[bf * C * C + (c0 + 1) * C + d] = make_float2(ar[11] * invN, ai[11] * invN);
        }
    }
#undef ACCP

    // init Y = X[:S], W = eye, H = 0
    for (int n = tid; n < N; n += NT) {
        gY[((b * S + 0) * F + f) * N + n] = Xs[0 * ROW + PAD + n];
        gY[((b * S + 1) * F + f) * N + n] = Xs[1 * ROW + PAD + n];
    }
    if (tid < S * C) {
        int s = tid / C, c = tid % C;
        gW[bf * S * C + tid] = make_float2((s == c) ? 1.f : 0.f, 0.f);
    }
    if (tid < S * C * T)
        gH[bf * S * C * T + tid] = make_float2(0.f, 0.f);
}

// ===========================================================================
// Kernel 2a: P[b,s,n] = sum_f |Y|^2   (deterministic, 32 blocks)
// ===========================================================================
__global__ void __launch_bounds__(256) k_ps() {
    const int bs = blockIdx.y;
    const int lane_n = threadIdx.x & 127;
    const int half = threadIdx.x >> 7;
    const int n = blockIdx.x * 125 + lane_n;
    __shared__ float sP[128];

    float acc = 0.f;
    if (lane_n < 125) {
        const float2* py = gY + (size_t)bs * F * N + n;
        int f0 = half ? 129 : 0;
        int f1 = half ? 257 : 129;
#pragma unroll 4
        for (int f = f0; f < f1; f++) {
            float2 v = py[(size_t)f * N];
            acc += v.x * v.x + v.y * v.y;
        }
    }
    if (half == 1) sP[lane_n] = acc;
    __syncthreads();
    if (half == 0 && lane_n < 125) gP[bs * N + n] = acc + sP[lane_n];
}

// ===========================================================================
// Kernel 2b: g, g_sqrt, weights from P  (4 tiny blocks)
// ===========================================================================
__global__ void __launch_bounds__(256) k_wt() {
    const int bs = blockIdx.x;
    const int tid = threadIdx.x;
    float p[4];
    float s = 0.f;
#pragma unroll
    for (int i = 0; i < 4; i++) {
        int n = tid + i * 256;
        p[i] = (n < N) ? gP[bs * N + n] : 0.f;
        s += p[i];
    }
    __shared__ float rr[8];
    __shared__ float g_sh;
#pragma unroll
    for (int off = 16; off > 0; off >>= 1) s += __shfl_down_sync(0xffffffffu, s, off);
    if ((tid & 31) == 0) rr[tid >> 5] = s;
    __syncthreads();
    if (tid == 0) {
        float tot = 0.f;
        for (int w = 0; w < 8; w++) tot += rr[w];
        float g = fmaxf(tot / (float)(F * N), EPS);
        g_sh = g;
        gGs[bs] = sqrtf(g);
    }
    __syncthreads();
    float g = g_sh;
#pragma unroll
    for (int i = 0; i < 4; i++) {
        int n = tid + i * 256;
        if (n < N) gWt[bs * N + n] = g / fmaxf(2.f * sqrtf(p[i]), MODEL_EPS);
    }
}

// ===========================================================================
// Kernel 3: one OverISS iteration per (b,f), Y/w register-resident
// ===========================================================================
template <int MODE>   // 0: src step, 1: background step, 2: tap step
DEVFN void iss_core(float2 (&xv)[4], float2 (&y0)[4], float2 (&y1)[4],
                    const float (&w0)[4], const float (&w1)[4],
                    float2* sW, float2* sH, const float2* sJ,
                    float2* sv, float* red,
                    int tid, int warp, int lane, int idx) {
    float s[6] = {0.f, 0.f, 0.f, 0.f, 0.f, 0.f};
#pragma unroll
    for (int i = 0; i < 4; i++) {
        float2 x = xv[i];
        float m = x.x * x.x + x.y * x.y;
        s[0] += w0[i] * (y0[i].x * x.x + y0[i].y * x.y);
        s[1] += w0[i] * (y0[i].y * x.x - y0[i].x * x.y);
        s[2] += w0[i] * m;
        s[3] += w1[i] * (y1[i].x * x.x + y1[i].y * x.y);
        s[4] += w1[i] * (y1[i].y * x.x - y1[i].x * x.y);
        s[5] += w1[i] * m;
    }
#pragma unroll
    for (int off = 16; off > 0; off >>= 1)
#pragma unroll
        for (int q = 0; q < 6; q++) s[q] += __shfl_down_sync(0xffffffffu, s[q], off);
    if (lane == 0)
#pragma unroll
        for (int q = 0; q < 6; q++) red[warp * 6 + q] = s[q];
    __syncthreads();
    if (tid == 0) {
        float t[6] = {0.f, 0.f, 0.f, 0.f, 0.f, 0.f};
        for (int w = 0; w < NT / 32; w++)
#pragma unroll
            for (int q = 0; q < 6; q++) t[q] += red[w * 6 + q];
        if (MODE == 0) {
            const float invN = 1.f / (float)N;
#pragma unroll
            for (int q = 0; q < 6; q++) t[q] *= invN;
        }
        float d0 = fmaxf(t[2], EPS), d1 = fmaxf(t[5], EPS);
        float2 v0 = make_float2(t[0] / d0, t[1] / d0);
        float2 v1 = make_float2(t[3] / d1, t[4] / d1);
        if (MODE == 0) {
            float ds = (idx == 0) ? t[2] : t[5];
            float vs = 1.f - 1.f / sqrtf(fmaxf(ds, EPS));
            if (idx == 0) v0 = make_float2(vs, 0.f);
            else          v1 = make_float2(vs, 0.f);
        }
        sv[0] = v0; sv[1] = v1;
    }
    __syncthreads();
    float2 v0 = sv[0], v1 = sv[1];
#pragma unroll
    for (int i = 0; i < 4; i++) {
        y0[i] = csub(y0[i], cmul(v0, xv[i]));
        y1[i] = csub(y1[i], cmul(v1, xv[i]));
    }
    if (MODE == 0) {
        if (tid < C) {
            float2 a = sW[idx * C + tid];               // old src row
            sW[tid]     = csub(sW[tid],     cmul(v0, a));
            sW[C + tid] = csub(sW[C + tid], cmul(v1, a));
        } else if (tid >= 32 && tid < 32 + C * T) {
            int j = tid - 32;
            float2 a = sH[idx * C * T + j];
            sH[j]           = csub(sH[j],           cmul(v0, a));
            sH[C * T + j]   = csub(sH[C * T + j],   cmul(v1, a));
        }
    } else if (MODE == 1) {
        if (tid < 2) {
            float2 v = tid ? v1 : v0;
            sW[tid * C + 0]       = csub(sW[tid * C + 0], cmul(v, sJ[idx * S + 0]));
            sW[tid * C + 1]       = csub(sW[tid * C + 1], cmul(v, sJ[idx * S + 1]));
            sW[tid * C + S + idx] = cadd(sW[tid * C + S + idx], v);
        }
    } else {
        if (tid < 2) {
            float2 v = tid ? v1 : v0;
            int d = idx / T, tp = idx % T;
            sH[(tid * C + d) * T + tp] = cadd(sH[(tid * C + d) * T + tp], v);
        }
    }
}

__global__ void __launch_bounds__(NT, 4) k_iter(const float* __restrict__ Xr,
                                                const float* __restrict__ Xi,
                                                int store) {
    extern __shared__ float2 smi[];
    float2* Xs = smi;                  // C*ROW
    float2* sW = Xs + C * ROW;         // S*C
    float2* sH = sW + S * C;           // S*C*T
    float2* sJ = sH + S * C * T;       // CB*S
    float2* sA = sJ + CB * S;          // S*C
    float2* sv = sA + S * C;           // 2
    float*  red = (float*)(sv + 2);    // 8*6

    const int bf = blockIdx.x;
    const int b = bf / F, f = bf % F;
    const int tid = threadIdx.x;
    const int warp = tid >> 5, lane = tid & 31;

    load_Xpad(Xs, Xr, Xi, b, f, tid);

    const float gs0 = gGs[b * S + 0];
    const float gs1 = gGs[b * S + 1];

    float2 y0[4], y1[4];
    float w0[4], w1[4];
#pragma unroll
    for (int i = 0; i < 4; i++) {
        int n = tid + i * NT;
        if (n < N) {
            float2 a = gY[((b * S + 0) * F + f) * N + n];
            float2 c = gY[((b * S + 1) * F + f) * N + n];
            y0[i] = make_float2(a.x / gs0, a.y / gs0);
            y1[i] = make_float2(c.x / gs1, c.y / gs1);
            w0[i] = gWt[(b * S + 0) * N + n];
            w1[i] = gWt[(b * S + 1) * N + n];
        } else {
            y0[i] = y1[i] = make_float2(0.f, 0.f);
            w0[i] = w1[i] = 0.f;
        }
    }
    if (tid < S * C) {
        float g = (tid < C) ? gs0 : gs1;
        float2 w = gW[bf * S * C + tid];
        sW[tid] = make_float2(w.x / g, w.y / g);
    }
    if (tid < S * C * T) {
        float g = (tid < C * T) ? gs0 : gs1;
        float2 h = gH[bf * S * C * T + tid];
        sH[tid] = make_float2(h.x / g, h.y / g);
    }
    __syncthreads();

    // --- background update: A = W C_XX + H C_XbarX ; 2x2 solve, 4 RHS ---
    if (tid < S * C) {
        int s = tid / C, d = tid % C;
        const float2* cxx = gCXX + bf * C * C;
        const float2* cbx = gCXbX + bf * C * T * C;
        float2 acc = make_float2(0.f, 0.f);
        for (int c = 0; c < C; c++) acc = cadd(acc, cmul(sW[s * C + c], cxx[c * C + d]));
        for (int dd = 0; dd < C; dd++)
            for (int t = 0; t < T; t++)
                acc = cadd(acc, cmul(sH[(s * C + dd) * T + t], cbx[(dd * T + t) * C + d]));
        sA[s * C + d] = acc;
    }
    __syncthreads();
    if (tid == 0) {
        float2 M00 = sA[0], M01 = sA[1], M10 = sA[C], M11 = sA[C + 1];
        float2 det = csub(cmul(M00, M11), cmul(M01, M10));
        for (int k = 0; k < CB; k++) {
            float2 r0 = sA[2 + k], r1 = sA[C + 2 + k];
            float2 jh0 = cdiv(csub(cmul(M11, r0), cmul(M01, r1)), det);
            float2 jh1 = cdiv(csub(cmul(M00, r1), cmul(M10, r0)), det);
            sJ[k * S + 0] = conjf2(jh0);
            sJ[k * S + 1] = conjf2(jh1);
        }
    }
    __syncthreads();

    // --- ISS steps: 2 src + 4 background + 30 taps ---
#pragma unroll 1
    for (int src = 0; src < S; src++) {
        float2 xv[4];
#pragma unroll
        for (int i = 0; i < 4; i++) xv[i] = src ? y1[i] : y0[i];
        iss_core<0>(xv, y0, y1, w0, w1, sW, sH, sJ, sv, red, tid, warp, lane, src);
    }
#pragma unroll 1
    for (int k = 0; k < CB; k++) {
        float2 j0 = sJ[k * S + 0], j1 = sJ[k * S + 1];
        float2 xv[4];
#pragma unroll
        for (int i = 0; i < 4; i++) {
            int n = tid + i * NT;
            float2 x0 = Xs[0 * ROW + PAD + n];
            float2 x1 = Xs[1 * ROW + PAD + n];
            float2 xb = Xs[(S + k) * ROW + PAD + n];
            xv[i] = csub(cadd(cmul(j0, x0), cmul(j1, x1)), xb);
        }
        iss_core<1>(xv, y0, y1, w0, w1, sW, sH, sJ, sv, red, tid, warp, lane, k);
    }
#pragma unroll 1
    for (int q = 0; q < C * T; q++) {
        const float2* xp = Xs + (q / T) * ROW + (q % T);
        float2 xv[4];
#pragma unroll
        for (int i = 0; i < 4; i++) xv[i] = xp[tid + i * NT];
        iss_core<2>(xv, y0, y1, w0, w1, sW, sH, sJ, sv, red, tid, warp, lane, q);
    }

    // --- write back ---
    if (store) {
#pragma unroll
        for (int i = 0; i < 4; i++) {
            int n = tid + i * NT;
            if (n < N) {
                gY[((b * S + 0) * F + f) * N + n] = y0[i];
                gY[((b * S + 1) * F + f) * N + n] = y1[i];
            }
        }
    }
    __syncthreads();   // filter updates (threads 0..1) must land before store
    if (tid < S * C) gW[bf * S * C + tid] = sW[tid];
    if (tid < S * C * T) gH[bf * S * C * T + tid] = sH[tid];
}

// ===========================================================================
// Kernel 4: final J, demix+derev, projection back, write output
// ===========================================================================
__global__ void __launch_bounds__(NT, 4) k_fin(const float* __restrict__ Xr,
                                               const float* __restrict__ Xi,
                                               float* __restrict__ out) {
    extern __shared__ float2 smf[];
    float2* Xs = smf;                 // C*ROW
    float2* sW = Xs + C * ROW;        // S*C
    float2* sH = sW + S * C;          // S*C*T
    float2* sJ = sH + S * C * T;      // CB*S
    float2* sA = sJ + CB * S;         // S*C
    float2* sa = sA + S * C;          // 2

    const int bf = blockIdx.x;
    const int b = bf / F, f = bf % F;
    const int tid = threadIdx.x;

    load_Xpad(Xs, Xr, Xi, b, f, tid);
    if (tid < S * C) sW[tid] = gW[bf * S * C + tid];
    if (tid < S * C * T) sH[tid] = gH[bf * S * C * T + tid];
    __syncthreads();

    if (tid < S * C) {
        int s = tid / C, d = tid % C;
        const float2* cxx = gCXX + bf * C * C;
        const float2* cbx = gCXbX + bf * C * T * C;
        float2 acc = make_float2(0.f, 0.f);
        for (int c = 0; c < C; c++) acc = cadd(acc, cmul(sW[s * C + c], cxx[c * C + d]));
        for (int dd = 0; dd < C; dd++)
            for (int t = 0; t < T; t++)
                acc = cadd(acc, cmul(sH[(s * C + dd) * T + t], cbx[(dd * T + t) * C + d]));
        sA[s * C + d] = acc;
    }
    __syncthreads();
    if (tid == 0) {
        float2 M00 = sA[0], M01 = sA[1], M10 = sA[C], M11 = sA[C + 1];
        float2 det = csub(cmul(M00, M11), cmul(M01, M10));
        for (int k = 0; k < CB; k++) {
            float2 r0 = sA[2 + k], r1 = sA[C + 2 + k];
            float2 jh0 = cdiv(csub(cmul(M11, r0), cmul(M01, r1)), det);
            float2 jh1 = cdiv(csub(cmul(M00, r1), cmul(M10, r0)), det);
            sJ[k * S + 0] = conjf2(jh0);
            sJ[k * S + 1] = conjf2(jh1);
        }
        float2 Bm[2][2];
        for (int s = 0; s < S; s++)
            for (int k = 0; k < S; k++) {
                float2 acc = sW[s * C + k];
                for (int c = 0; c < CB; c++)
                    acc = cadd(acc, cmul(sW[s * C + S + c], sJ[c * S + k]));
                Bm[s][k] = acc;
            }
        float2 P00 = make_float2(Bm[0][0].x + PB_EPS, Bm[0][0].y);
        float2 P01 = Bm[1][0];
        float2 P10 = Bm[0][1];
        float2 P11 = make_float2(Bm[1][1].x + PB_EPS, Bm[1][1].y);
        float2 pdet = csub(cmul(P00, P11), cmul(P01, P10));
        sa[0] = cdiv(P11, pdet);
        sa[1] = cdiv(make_float2(-P10.x, -P10.y), pdet);
    }
    __syncthreads();

    float2 a0 = sa[0], a1 = sa[1];
    for (int n = tid; n < N; n += NT) {
#pragma unroll
        for (int s = 0; s < S; s++) {
            float2 y = make_float2(0.f, 0.f);
            for (int d = 0; d < C; d++)
                y = cadd(y, cmul(sW[s * C + d], Xs[d * ROW + PAD + n]));
            for (int d = 0; d < C; d++)
#pragma unroll
                for (int t = 0; t < T; t++)
                    y = csub(y, cmul(sH[(s * C + d) * T + t], Xs[d * ROW + t + n]));
            y = cmul(y, (s == 0) ? a0 : a1);
            size_t oi = ((size_t)((b * S + s) * F + f) * N + n) * 2;
            out[oi]     = y.x;
            out[oi + 1] = y.y;
        }
    }
}

// ===========================================================================
// launch
// ===========================================================================
namespace {
constexpr size_t SMEM_PRE  = sizeof(float2) * (size_t)(C * ROW);
constexpr size_t SMEM_ITER = sizeof(float2) * (size_t)(C * ROW + S * C + S * C * T +
                                                       CB * S + S * C + 2)
                           + sizeof(float) * 48;
constexpr size_t SMEM_FIN  = sizeof(float2) * (size_t)(C * ROW + S * C + S * C * T +
                                                       CB * S + S * C + 2);
}

extern "C" void kernel_launch(void* const* d_in, const int* in_sizes, int n_in,
                              void* d_out, int out_size) {
    (void)in_sizes; (void)n_in; (void)out_size;
    const float* Xr = (const float*)d_in[0];
    const float* Xi = (const float*)d_in[1];
    float* out = (float*)d_out;

    cudaFuncSetAttribute(k_pre,  cudaFuncAttributeMaxDynamicSharedMemorySize, (int)SMEM_PRE);
    cudaFuncSetAttribute(k_iter, cudaFuncAttributeMaxDynamicSharedMemorySize, (int)SMEM_ITER);
    cudaFuncSetAttribute(k_fin,  cudaFuncAttributeMaxDynamicSharedMemorySize, (int)SMEM_FIN);

    k_pre<<<NBF, NT, SMEM_PRE>>>(Xr, Xi);
    for (int it = 0; it < 2; it++) {
        k_ps<<<dim3(8, B * S), 256>>>();
        k_wt<<<B * S, 256>>>();
        k_iter<<<NBF, NT, SMEM_ITER>>>(Xr, Xi, it == 0 ? 1 : 0);
    }
    k_fin<<<NBF, NT, SMEM_FIN>>>(Xr, Xi, out);
}

// round 3
// speedup vs baseline: 2.1609x; 1.0378x over previous
#include <cuda_runtime.h>

// ---------------------------------------------------------------------------
// OverISS_T, R3: fused pipeline, one-sync-per-ISS-step with redundant
// all-thread v computation (no serial tid0 section), double-buffered
// reduction scratch, parallel weight reduction.
// ---------------------------------------------------------------------------

#define DEVFN __device__ __forceinline__

namespace cfg {
constexpr int B = 2, C = 6, S = 2, F = 257, N = 1000, T = 5;
constexpr int CB = C - S;
constexpr int PAD = 6;
constexpr int ROW = 1032;
constexpr int NBF = B * F;
constexpr int NT = 256;
constexpr float EPS = 1e-3f;
constexpr float MODEL_EPS = 1e-5f;
constexpr float PB_EPS = 1e-6f;
}
using namespace cfg;

// ------------------------- global scratch -------------------------
__device__ float2 gY[B * S * F * N];
__device__ float2 gW[B * F * S * C];
__device__ float2 gH[B * F * S * C * T];
__device__ float2 gCXX[B * F * C * C];
__device__ float2 gCXbX[B * F * C * T * C];
__device__ float  gWt[B * S * N];
__device__ float  gPp[4 * B * S * N];      // per-f-chunk partial power
__device__ float  gGs[B * S];

// ------------------------- complex helpers -------------------------
DEVFN float2 cmul(float2 a, float2 b) { return make_float2(a.x*b.x - a.y*b.y, a.x*b.y + a.y*b.x); }
DEVFN float2 cadd(float2 a, float2 b) { return make_float2(a.x + b.x, a.y + b.y); }
DEVFN float2 csub(float2 a, float2 b) { return make_float2(a.x - b.x, a.y - b.y); }
DEVFN float2 conjf2(float2 a)         { return make_float2(a.x, -a.y); }
DEVFN float2 cdiv(float2 a, float2 b) {
    float d = b.x*b.x + b.y*b.y;
    return make_float2((a.x*b.x + a.y*b.y) / d, (a.y*b.x - a.x*b.y) / d);
}

DEVFN void load_Xpad(float2* Xs, const float* __restrict__ Xr,
                     const float* __restrict__ Xi, int b, int f, int tid) {
    for (int i = tid; i < C * ROW; i += NT) {
        int d = i / ROW, j = i % ROW;
        float2 v = make_float2(0.f, 0.f);
        if (j >= PAD && j < PAD + N) {
            int gi = ((b * C + d) * F + f) * N + (j - PAD);
            v = make_float2(Xr[gi], Xi[gi]);
        }
        Xs[i] = v;
    }
}

// ------------------------- shared building blocks -------------------------
DEVFN void bg_update(const float2* sW, const float2* sH, const float2* sXX,
                     const float2* sXbX, float2* sA, int tid) {
    if (tid < S * C) {
        int s = tid / C, d = tid % C;
        float2 acc = make_float2(0.f, 0.f);
        for (int c = 0; c < C; c++) acc = cadd(acc, cmul(sW[s * C + c], sXX[c * C + d]));
        for (int dd = 0; dd < C; dd++)
#pragma unroll
            for (int t = 0; t < T; t++)
                acc = cadd(acc, cmul(sH[(s * C + dd) * T + t], sXbX[(dd * T + t) * C + d]));
        sA[s * C + d] = acc;
    }
}

DEVFN void solveJ(const float2* sA, float2* sJ) {
    float2 M00 = sA[0], M01 = sA[1], M10 = sA[C], M11 = sA[C + 1];
    float2 det = csub(cmul(M00, M11), cmul(M01, M10));
#pragma unroll
    for (int k = 0; k < CB; k++) {
        float2 r0 = sA[2 + k], r1 = sA[C + 2 + k];
        float2 jh0 = cdiv(csub(cmul(M11, r0), cmul(M01, r1)), det);
        float2 jh1 = cdiv(csub(cmul(M00, r1), cmul(M10, r0)), det);
        sJ[k * S + 0] = conjf2(jh0);
        sJ[k * S + 1] = conjf2(jh1);
    }
}

// One ISS step. ONE __syncthreads; every thread redundantly computes the
// final reduction + v (identical IEEE ops -> identical values).
template <int MODE>   // 0: src step, 1: background step, 2: tap step
DEVFN void iss_core(const float2 (&xv)[4], float2 (&y0)[4], float2 (&y1)[4],
                    const float (&w0)[4], const float (&w1)[4],
                    float2* sW, float2* sH, const float2* sJ, float* red,
                    int parity, int tid, int warp, int lane, int idx) {
    float s0 = 0.f, s1 = 0.f, s2 = 0.f, s3 = 0.f, s4 = 0.f, s5 = 0.f;
#pragma unroll
    for (int i = 0; i < 4; i++) {
        float2 x = xv[i];
        float m = x.x * x.x + x.y * x.y;
        s0 += w0[i] * (y0[i].x * x.x + y0[i].y * x.y);
        s1 += w0[i] * (y0[i].y * x.x - y0[i].x * x.y);
        s2 += w0[i] * m;
        s3 += w1[i] * (y1[i].x * x.x + y1[i].y * x.y);
        s4 += w1[i] * (y1[i].y * x.x - y1[i].x * x.y);
        s5 += w1[i] * m;
    }
#pragma unroll
    for (int off = 16; off > 0; off >>= 1) {
        s0 += __shfl_down_sync(0xffffffffu, s0, off);
        s1 += __shfl_down_sync(0xffffffffu, s1, off);
        s2 += __shfl_down_sync(0xffffffffu, s2, off);
        s3 += __shfl_down_sync(0xffffffffu, s3, off);
        s4 += __shfl_down_sync(0xffffffffu, s4, off);
        s5 += __shfl_down_sync(0xffffffffu, s5, off);
    }
    if (lane == 0) {
        float* r = red + parity * 64 + warp * 8;
        r[0] = s0; r[1] = s1; r[2] = s2; r[3] = s3; r[4] = s4; r[5] = s5;
    }
    __syncthreads();
    float t0 = 0.f, t1 = 0.f, t2 = 0.f, t3 = 0.f, t4 = 0.f, t5 = 0.f;
    {
        const float4* r4 = (const float4*)(red + parity * 64);
#pragma unroll
        for (int w = 0; w < NT / 32; w++) {
            float4 a = r4[2 * w], bb = r4[2 * w + 1];
            t0 += a.x; t1 += a.y; t2 += a.z; t3 += a.w; t4 += bb.x; t5 += bb.y;
        }
    }
    if (MODE == 0) {
        const float invN = 1.f / (float)N;
        t0 *= invN; t1 *= invN; t2 *= invN; t3 *= invN; t4 *= invN; t5 *= invN;
    }
    float d0 = fmaxf(t2, EPS), d1 = fmaxf(t5, EPS);
    float2 v0 = make_float2(t0 / d0, t1 / d0);
    float2 v1 = make_float2(t3 / d1, t4 / d1);
    if (MODE == 0) {
        float ds = (idx == 0) ? t2 : t5;
        float vs = 1.f - 1.f / sqrtf(fmaxf(ds, EPS));
        if (idx == 0) v0 = make_float2(vs, 0.f);
        else          v1 = make_float2(vs, 0.f);
    }
#pragma unroll
    for (int i = 0; i < 4; i++) {
        y0[i] = csub(y0[i], cmul(v0, xv[i]));
        y1[i] = csub(y1[i], cmul(v1, xv[i]));
    }
    if (MODE == 0) {
        if (tid < C) {
            float2 a = sW[idx * C + tid];
            sW[tid]     = csub(sW[tid],     cmul(v0, a));
            sW[C + tid] = csub(sW[C + tid], cmul(v1, a));
        } else if (tid >= 32 && tid < 32 + C * T) {
            int j = tid - 32;
            float2 a = sH[idx * C * T + j];
            sH[j]         = csub(sH[j],         cmul(v0, a));
            sH[C * T + j] = csub(sH[C * T + j], cmul(v1, a));
        }
    } else if (MODE == 1) {
        if (tid < 2) {
            float2 v = tid ? v1 : v0;
            sW[tid * C + 0]       = csub(sW[tid * C + 0], cmul(v, sJ[idx * S + 0]));
            sW[tid * C + 1]       = csub(sW[tid * C + 1], cmul(v, sJ[idx * S + 1]));
            sW[tid * C + S + idx] = cadd(sW[tid * C + S + idx], v);
        }
    } else {
        if (tid < 2) {
            float2 v = tid ? v1 : v0;
            int d = idx / T, tp = idx % T;
            sH[(tid * C + d) * T + tp] = cadd(sH[(tid * C + d) * T + tp], v);
        }
    }
}

DEVFN void run_steps(const float2* Xs, float2* sW, float2* sH, const float2* sJ,
                     float* red, float2 (&y0)[4], float2 (&y1)[4],
                     const float (&w0)[4], const float (&w1)[4],
                     int tid, int warp, int lane) {
    int par = 0;
#pragma unroll 1
    for (int src = 0; src < S; src++) {
        float2 xv[4];
#pragma unroll
        for (int i = 0; i < 4; i++) xv[i] = src ? y1[i] : y0[i];
        iss_core<0>(xv, y0, y1, w0, w1, sW, sH, sJ, red, par, tid, warp, lane, src);
        par ^= 1;
    }
#pragma unroll 1
    for (int k = 0; k < CB; k++) {
        float2 j0 = sJ[k * S + 0], j1 = sJ[k * S + 1];
        float2 xv[4];
#pragma unroll
        for (int i = 0; i < 4; i++) {
            int n = tid + i * NT;
            float2 x0 = Xs[0 * ROW + PAD + n];
            float2 x1 = Xs[1 * ROW + PAD + n];
            float2 xb = Xs[(S + k) * ROW + PAD + n];
            xv[i] = csub(cadd(cmul(j0, x0), cmul(j1, x1)), xb);
        }
        iss_core<1>(xv, y0, y1, w0, w1, sW, sH, sJ, red, par, tid, warp, lane, k);
        par ^= 1;
    }
#pragma unroll 1
    for (int q = 0; q < C * T; q++) {
        const float2* xp = Xs + (q / T) * ROW + (q % T);
        float2 xv[4];
#pragma unroll
        for (int i = 0; i < 4; i++) xv[i] = xp[tid + i * NT];
        iss_core<2>(xv, y0, y1, w0, w1, sW, sH, sJ, red, par, tid, warp, lane, q);
        par ^= 1;
    }
}

// ===========================================================================
// Weight reduction: per-f-chunk partial power (128 blocks), then tiny k_wt
// ===========================================================================
__global__ void __launch_bounds__(128) k_ps0(const float* __restrict__ Xr,
                                             const float* __restrict__ Xi) {
    const int tid = threadIdx.x;
    if (tid >= 125) return;
    const int n = blockIdx.x * 125 + tid;
    const int bs = blockIdx.y;
    const int ch = blockIdx.z;
    const int b = bs / S, s = bs % S;
    const size_t base = ((size_t)(b * C + s) * F) * N + n;
    const int f0 = ch * 65, f1 = (f0 + 65 < F) ? f0 + 65 : F;
    float acc = 0.f;
    for (int f = f0; f < f1; f++) {
        float r = Xr[base + (size_t)f * N];
        float im = Xi[base + (size_t)f * N];
        acc += r * r + im * im;
    }
    gPp[(ch * B * S + bs) * N + n] = acc;
}

__global__ void __launch_bounds__(128) k_psY() {
    const int tid = threadIdx.x;
    if (tid >= 125) return;
    const int n = blockIdx.x * 125 + tid;
    const int bs = blockIdx.y;
    const int ch = blockIdx.z;
    const float2* py = gY + (size_t)bs * F * N + n;
    const int f0 = ch * 65, f1 = (f0 + 65 < F) ? f0 + 65 : F;
    float acc = 0.f;
    for (int f = f0; f < f1; f++) {
        float2 v = py[(size_t)f * N];
        acc += v.x * v.x + v.y * v.y;
    }
    gPp[(ch * B * S + bs) * N + n] = acc;
}

__global__ void __launch_bounds__(256) k_wt() {
    const int bs = blockIdx.x;
    const int tid = threadIdx.x;
    float p[4];
    float s = 0.f;
#pragma unroll
    for (int i = 0; i < 4; i++) {
        int n = tid + i * 256;
        float acc = 0.f;
        if (n < N) {
#pragma unroll
            for (int ch = 0; ch < 4; ch++) acc += gPp[(ch * B * S + bs) * N + n];
        }
        p[i] = acc;
        s += acc;
    }
    __shared__ float rr[8];
    __shared__ float g_sh;
#pragma unroll
    for (int off = 16; off > 0; off >>= 1) s += __shfl_down_sync(0xffffffffu, s, off);
    if ((tid & 31) == 0) rr[tid >> 5] = s;
    __syncthreads();
    if (tid == 0) {
        float tot = 0.f;
        for (int w = 0; w < 8; w++) tot += rr[w];
        float g = fmaxf(tot / (float)(F * N), EPS);
        g_sh = g;
        gGs[bs] = sqrtf(g);
    }
    __syncthreads();
    float g = g_sh;
#pragma unroll
    for (int i = 0; i < 4; i++) {
        int n = tid + i * 256;
        if (n < N) gWt[bs * N + n] = g / fmaxf(2.f * sqrtf(p[i]), MODEL_EPS);
    }
}

// ===========================================================================
// k_first: covariances + iteration 1 (X loaded once)
// ===========================================================================
__global__ void __launch_bounds__(NT, 4) k_first(const float* __restrict__ Xr,
                                                 const float* __restrict__ Xi) {
    extern __shared__ float2 sm1[];
    float2* Xs   = sm1;                 // C*ROW
    float2* sW   = Xs + C * ROW;        // 12
    float2* sH   = sW + S * C;          // 60
    float2* sJ   = sH + S * C * T;      // 8
    float2* sA   = sJ + CB * S;         // 12
    float2* sXX  = sA + S * C;          // 36
    float2* sXbX = sXX + C * C;         // 180
    float*  red  = (float*)(sXbX + C * T * C);  // 128

    const int bf = blockIdx.x;
    const int b = bf / F, f = bf % F;
    const int tid = threadIdx.x;
    const int warp = tid >> 5, lane = tid & 31;

    load_Xpad(Xs, Xr, Xi, b, f, tid);

    const float gs0 = gGs[b * S + 0];
    const float gs1 = gGs[b * S + 1];
    const float i0 = 1.f / gs0, i1 = 1.f / gs1;

    if (tid < S * C) {
        int s = tid / C, c = tid % C;
        sW[tid] = make_float2((s == c) ? ((s == 0) ? i0 : i1) : 0.f, 0.f);
    }
    if (tid < S * C * T) sH[tid] = make_float2(0.f, 0.f);
    __syncthreads();

    // ---- covariances: 18 (d, c-pair) groups, 12 outputs each ----
#define ACCP(j, A, Bv) { ar[j] += (A).x*(Bv).x + (A).y*(Bv).y; \
                         ai[j] += (A).y*(Bv).x - (A).x*(Bv).y; }
#pragma unroll 1
    for (int g = warp; g < 18; g += NT / 32) {
        int d = g / 3, p = g % 3, c0 = 2 * p;
        const float2* ad = Xs + d * ROW;
        const float2* b0 = Xs + c0 * ROW + PAD;
        const float2* b1 = b0 + ROW;
        float ar[12], ai[12];
#pragma unroll
        for (int j = 0; j < 12; j++) { ar[j] = 0.f; ai[j] = 0.f; }
        for (int n = lane; n < N; n += 32) {
            float2 a0 = ad[n], a1 = ad[n+1], a2 = ad[n+2], a3 = ad[n+3], a4 = ad[n+4];
            float2 a6 = ad[n+6];
            float2 u = b0[n], v = b1[n];
            ACCP(0, a0, u); ACCP(1, a1, u); ACCP(2, a2, u); ACCP(3, a3, u); ACCP(4, a4, u);
            ACCP(5, a0, v); ACCP(6, a1, v); ACCP(7, a2, v); ACCP(8, a3, v); ACCP(9, a4, v);
            ACCP(10, u, a6); ACCP(11, v, a6);
        }
#pragma unroll
        for (int off = 16; off > 0; off >>= 1)
#pragma unroll
            for (int j = 0; j < 12; j++) {
                ar[j] += __shfl_down_sync(0xffffffffu, ar[j], off);
                ai[j] += __shfl_down_sync(0xffffffffu, ai[j], off);
            }
        if (lane == 0) {
            const float invN = 1.f / (float)N;
#pragma unroll
            for (int t = 0; t < T; t++) {
                float2 v0 = make_float2(ar[t] * invN, ai[t] * invN);
                float2 v1 = make_float2(ar[5 + t] * invN, ai[5 + t] * invN);
                sXbX[(d * T + t) * C + c0]     = v0;
                sXbX[(d * T + t) * C + c0 + 1] = v1;
                gCXbX[bf * C * T * C + (d * T + t) * C + c0]     = v0;
                gCXbX[bf * C * T * C + (d * T + t) * C + c0 + 1] = v1;
            }
            float2 x0 = make_float2(ar[10] * invN, ai[10] * invN);
            float2 x1 = make_float2(ar[11] * invN, ai[11] * invN);
            sXX[c0 * C + d]       = x0;
            sXX[(c0 + 1) * C + d] = x1;
            gCXX[bf * C * C + c0 * C + d]       = x0;
            gCXX[bf * C * C + (c0 + 1) * C + d] = x1;
        }
    }
#undef ACCP

    // ---- Y, weights registers (Y init = X[:S] scaled) ----
    float2 y0[4], y1[4];
    float w0[4], w1[4];
#pragma unroll
    for (int i = 0; i < 4; i++) {
        int n = tid + i * NT;
        if (n < N) {
            float2 a = Xs[0 * ROW + PAD + n];
            float2 c = Xs[1 * ROW + PAD + n];
            y0[i] = make_float2(a.x * i0, a.y * i0);
            y1[i] = make_float2(c.x * i1, c.y * i1);
            w0[i] = gWt[(b * S + 0) * N + n];
            w1[i] = gWt[(b * S + 1) * N + n];
        } else {
            y0[i] = y1[i] = make_float2(0.f, 0.f);
            w0[i] = w1[i] = 0.f;
        }
    }
    __syncthreads();

    bg_update(sW, sH, sXX, sXbX, sA, tid);
    __syncthreads();
    if (tid == 0) solveJ(sA, sJ);
    __syncthreads();

    run_steps(Xs, sW, sH, sJ, red, y0, y1, w0, w1, tid, warp, lane);
    __syncthreads();

#pragma unroll
    for (int i = 0; i < 4; i++) {
        int n = tid + i * NT;
        if (n < N) {
            gY[((b * S + 0) * F + f) * N + n] = y0[i];
            gY[((b * S + 1) * F + f) * N + n] = y1[i];
        }
    }
    if (tid < S * C) gW[bf * S * C + tid] = sW[tid];
    if (tid < S * C * T) gH[bf * S * C * T + tid] = sH[tid];
}

// ===========================================================================
// k_last: iteration 2 + final J + demix/derev + projection back + output
// ===========================================================================
__global__ void __launch_bounds__(NT, 4) k_last(const float* __restrict__ Xr,
                                                const float* __restrict__ Xi,
                                                float* __restrict__ out) {
    extern __shared__ float2 sm2[];
    float2* Xs   = sm2;
    float2* sW   = Xs + C * ROW;
    float2* sH   = sW + S * C;
    float2* sJ   = sH + S * C * T;
    float2* sA   = sJ + CB * S;
    float2* sXX  = sA + S * C;
    float2* sXbX = sXX + C * C;
    float*  red  = (float*)(sXbX + C * T * C);

    const int bf = blockIdx.x;
    const int b = bf / F, f = bf % F;
    const int tid = threadIdx.x;
    const int warp = tid >> 5, lane = tid & 31;

    load_Xpad(Xs, Xr, Xi, b, f, tid);

    const float gs0 = gGs[b * S + 0];
    const float gs1 = gGs[b * S + 1];
    const float i0 = 1.f / gs0, i1 = 1.f / gs1;

    if (tid < S * C) {
        float iv = (tid < C) ? i0 : i1;
        float2 w = gW[bf * S * C + tid];
        sW[tid] = make_float2(w.x * iv, w.y * iv);
    }
    if (tid < S * C * T) {
        float iv = (tid < C * T) ? i0 : i1;
        float2 h = gH[bf * S * C * T + tid];
        sH[tid] = make_float2(h.x * iv, h.y * iv);
    }
    if (tid < C * C) sXX[tid] = gCXX[bf * C * C + tid];
    if (tid < C * T * C) sXbX[tid] = gCXbX[bf * C * T * C + tid];

    float2 y0[4], y1[4];
    float w0[4], w1[4];
#pragma unroll
    for (int i = 0; i < 4; i++) {
        int n = tid + i * NT;
        if (n < N) {
            float2 a = gY[((b * S + 0) * F + f) * N + n];
            float2 c = gY[((b * S + 1) * F + f) * N + n];
            y0[i] = make_float2(a.x * i0, a.y * i0);
            y1[i] = make_float2(c.x * i1, c.y * i1);
            w0[i] = gWt[(b * S + 0) * N + n];
            w1[i] = gWt[(b * S + 1) * N + n];
        } else {
            y0[i] = y1[i] = make_float2(0.f, 0.f);
            w0[i] = w1[i] = 0.f;
        }
    }
    __syncthreads();

    bg_update(sW, sH, sXX, sXbX, sA, tid);
    __syncthreads();
    if (tid == 0) solveJ(sA, sJ);
    __syncthreads();

    run_steps(Xs, sW, sH, sJ, red, y0, y1, w0, w1, tid, warp, lane);
    __syncthreads();

    // final background update with updated W, H
    bg_update(sW, sH, sXX, sXbX, sA, tid);
    __syncthreads();
    if (tid == 0) {
        solveJ(sA, sJ);
        // projection back: B[s][k] = W1[s][k] + sum_c W2[s][c] J[c][k]
        float2 Bm[2][2];
#pragma unroll
        for (int s = 0; s < S; s++)
#pragma unroll
            for (int k = 0; k < S; k++) {
                float2 acc = sW[s * C + k];
                for (int c = 0; c < CB; c++)
                    acc = cadd(acc, cmul(sW[s * C + S + c], sJ[c * S + k]));
                Bm[s][k] = acc;
            }
        float2 P00 = make_float2(Bm[0][0].x + PB_EPS, Bm[0][0].y);
        float2 P01 = Bm[1][0];
        float2 P10 = Bm[0][1];
        float2 P11 = make_float2(Bm[1][1].x + PB_EPS, Bm[1][1].y);
        float2 pdet = csub(cmul(P00, P11), cmul(P01, P10));
        sA[0] = cdiv(P11, pdet);
        sA[1] = cdiv(make_float2(-P10.x, -P10.y), pdet);
    }
    __syncthreads();

    // demix + derev + projection, write output
    float2 a0 = sA[0], a1 = sA[1];
    for (int n = tid; n < N; n += NT) {
#pragma unroll
        for (int s = 0; s < S; s++) {
            float2 y = make_float2(0.f, 0.f);
            for (int d = 0; d < C; d++) {
                const float2* xr = Xs + d * ROW + n;    // row base at tap offset
                y = cadd(y, cmul(sW[s * C + d], xr[PAD]));
#pragma unroll
                for (int t = 0; t < T; t++)
                    y = csub(y, cmul(sH[(s * C + d) * T + t], xr[t]));
            }
            y = cmul(y, (s == 0) ? a0 : a1);
            size_t oi = ((size_t)((b * S + s) * F + f) * N + n) * 2;
            out[oi]     = y.x;
            out[oi + 1] = y.y;
        }
    }
}

// ===========================================================================
// launch
// ===========================================================================
namespace {
constexpr size_t SMEM_MAIN = sizeof(float2) * (size_t)(C * ROW + S * C + S * C * T +
                                                       CB * S + S * C + C * C + C * T * C)
                           + sizeof(float) * 128;
}

extern "C" void kernel_launch(void* const* d_in, const int* in_sizes, int n_in,
                              void* d_out, int out_size) {
    (void)in_sizes; (void)n_in; (void)out_size;
    const float* Xr = (const float*)d_in[0];
    const float* Xi = (const float*)d_in[1];
    float* out = (float*)d_out;

    cudaFuncSetAttribute(k_first, cudaFuncAttributeMaxDynamicSharedMemorySize, (int)SMEM_MAIN);
    cudaFuncSetAttribute(k_last,  cudaFuncAttributeMaxDynamicSharedMemorySize, (int)SMEM_MAIN);

    k_ps0<<<dim3(8, B * S, 4), 128>>>(Xr, Xi);
    k_wt<<<B * S, 256>>>();
    k_first<<<NBF, NT, SMEM_MAIN>>>(Xr, Xi);
    k_psY<<<dim3(8, B * S, 4), 128>>>();
    k_wt<<<B * S, 256>>>();
    k_last<<<NBF, NT, SMEM_MAIN>>>(Xr, Xi, out);
}